// round 1
// baseline (speedup 1.0000x reference)
#include <cuda_runtime.h>

#define HH 80
#define WW 80
#define HWSZ 6400
#define NB 2
#define CI 64

// ---------------- scratch (__device__ globals; no allocation) ----------------
__device__ float g_off3[NB * 18 * HWSZ];
__device__ float g_mask3[NB * 9 * HWSZ];
__device__ float g_off5[NB * 50 * HWSZ];
__device__ float g_mask5[NB * 25 * HWSZ];
__device__ float g_off7[NB * 98 * HWSZ];
__device__ float g_mask7[NB * 49 * HWSZ];
__device__ float g_wt3[9 * 64 * 64];    // [t][c][oc]
__device__ float g_wt5[25 * 64 * 64];
__device__ float g_wt7[49 * 64 * 64];

template <int K> __device__ __forceinline__ float* off_buf() {
    if constexpr (K == 3) return g_off3;
    else if constexpr (K == 5) return g_off5;
    else return g_off7;
}
template <int K> __device__ __forceinline__ float* mask_buf() {
    if constexpr (K == 3) return g_mask3;
    else if constexpr (K == 5) return g_mask5;
    else return g_mask7;
}
template <int K> __device__ __forceinline__ float* wt_buf() {
    if constexpr (K == 3) return g_wt3;
    else if constexpr (K == 5) return g_wt5;
    else return g_wt7;
}

// ---------------- transpose w_dcn (OC,C,k,k) -> (t,c,oc) ----------------
template <int K>
__global__ __launch_bounds__(256) void transpose_w(const float* __restrict__ w) {
    constexpr int KK = K * K;
    int idx = blockIdx.x * 256 + threadIdx.x;
    if (idx >= KK * 64 * 64) return;
    int oc = idx & 63;
    int rem = idx >> 6;
    int c = rem & 63;
    int t = rem >> 6;
    wt_buf<K>()[idx] = w[(oc * 64 + c) * KK + t];
}

// ---------------- fused offset+mask conv (implicit GEMM) ----------------
// Block: 256 threads, 64 pixels x 32 output channels, reduction over 64*K*K.
template <int K>
__global__ __launch_bounds__(256) void conv_offmask(
    const float* __restrict__ x,
    const float* __restrict__ w_off, const float* __restrict__ b_off,
    const float* __restrict__ w_mask, const float* __restrict__ b_mask) {
    constexpr int KK = K * K;
    constexpr int OC = 3 * KK;
    constexpr int P = K / 2;
    constexpr int R = CI * KK;
    constexpr int OCT = 32;
    constexpr int AST = OCT + 4;  // 36: 16B-aligned rows, low bank conflict

    __shared__ float As[16 * AST];
    __shared__ float Bs[16 * 64];

    const int tid = threadIdx.x;
    const int b = blockIdx.z;
    const int pbase = blockIdx.x * 64;
    const int ocbase = blockIdx.y * OCT;

    // staging pixel (fixed per thread)
    const int sp = tid & 63;
    const int shw = pbase + sp;
    const int sh = shw / WW;
    const int sw = shw - sh * WW;
    const float* xb = x + b * CI * HWSZ;

    const int oc0 = (tid >> 4) * 2;   // 0..30
    const int p0 = (tid & 15) * 4;    // 0..60

    float acc[2][4];
#pragma unroll
    for (int i = 0; i < 2; ++i)
#pragma unroll
        for (int l = 0; l < 4; ++l) acc[i][l] = 0.f;

    const int aj = tid & 15;          // A staging row (fixed)
    const int ai = tid >> 4;          // A staging col base

#pragma unroll 2
    for (int rbase = 0; rbase < R; rbase += 16) {
        __syncthreads();
        // stage B: gathered input patch values [16 r][64 p]
#pragma unroll
        for (int s = 0; s < 4; ++s) {
            int j = (tid >> 6) + 4 * s;
            int r = rbase + j;
            int ci = r / KK;
            int t = r - ci * KK;
            int ky = t / K;
            int kx = t - ky * K;
            int y = sh + ky - P;
            int xx = sw + kx - P;
            float v = 0.f;
            if (y >= 0 && y < HH && xx >= 0 && xx < WW)
                v = __ldg(xb + ci * HWSZ + y * WW + xx);
            Bs[j * 64 + sp] = v;
        }
        // stage A: weights [16 r][32 oc] (r contiguous in memory -> coalesced)
#pragma unroll
        for (int s = 0; s < 2; ++s) {
            int i = ai + 16 * s;
            int r = rbase + aj;
            int oc = ocbase + i;
            float v = 0.f;
            if (oc < 2 * KK) v = __ldg(w_off + oc * R + r);
            else if (oc < OC) v = __ldg(w_mask + (oc - 2 * KK) * R + r);
            As[aj * AST + i] = v;
        }
        __syncthreads();
#pragma unroll
        for (int j = 0; j < 16; ++j) {
            const float2 a = *(const float2*)(As + j * AST + oc0);
            const float4 bv = *(const float4*)(Bs + j * 64 + p0);
            acc[0][0] += a.x * bv.x; acc[0][1] += a.x * bv.y;
            acc[0][2] += a.x * bv.z; acc[0][3] += a.x * bv.w;
            acc[1][0] += a.y * bv.x; acc[1][1] += a.y * bv.y;
            acc[1][2] += a.y * bv.z; acc[1][3] += a.y * bv.w;
        }
    }

    // epilogue: bias, (sigmoid for mask part), write to scratch
    const int hw = pbase + p0;
#pragma unroll
    for (int i = 0; i < 2; ++i) {
        int oc = ocbase + oc0 + i;
        if (oc >= OC) continue;
        if (oc < 2 * KK) {
            float bias = __ldg(b_off + oc);
            float4 v = make_float4(acc[i][0] + bias, acc[i][1] + bias,
                                   acc[i][2] + bias, acc[i][3] + bias);
            *(float4*)(off_buf<K>() + (b * 2 * KK + oc) * HWSZ + hw) = v;
        } else {
            float bias = __ldg(b_mask + (oc - 2 * KK));
            float4 v;
            v.x = 1.f / (1.f + __expf(-(acc[i][0] + bias)));
            v.y = 1.f / (1.f + __expf(-(acc[i][1] + bias)));
            v.z = 1.f / (1.f + __expf(-(acc[i][2] + bias)));
            v.w = 1.f / (1.f + __expf(-(acc[i][3] + bias)));
            *(float4*)(mask_buf<K>() + (b * KK + (oc - 2 * KK)) * HWSZ + hw) = v;
        }
    }
}

// ---------------- fused deformable sampling + GEMM ----------------
// Block: 256 threads, 64 pixels x 64 output channels.
// Reduction over (t in KK) x (c in 64); per-t bilinear descriptors cached in smem.
template <int K, int BROFF>
__global__ __launch_bounds__(256) void deform_gemm(
    const float* __restrict__ x, float* __restrict__ out) {
    constexpr int KK = K * K;
    constexpr int P = K / 2;
    constexpr int AST = 68;

    __shared__ float Ws[16 * AST];
    __shared__ float Bs[16 * 64];
    __shared__ float4 sW[64];
    __shared__ int4 sI[64];

    const int tid = threadIdx.x;
    const int b = blockIdx.y;
    const int pbase = blockIdx.x * 64;

    const int sp = tid & 63;
    const float* xb = x + b * CI * HWSZ;
    const float* wt = wt_buf<K>();
    const float* goff = off_buf<K>();
    const float* gmask = mask_buf<K>();

    const int oc0 = (tid >> 4) * 4;
    const int p0 = (tid & 15) * 4;

    float acc[4][4];
#pragma unroll
    for (int i = 0; i < 4; ++i)
#pragma unroll
        for (int l = 0; l < 4; ++l) acc[i][l] = 0.f;

    for (int t = 0; t < KK; ++t) {
        __syncthreads();
        if (tid < 64) {
            // bilinear descriptor for pixel tid at tap t
            int hw = pbase + tid;
            int h = hw / WW;
            int w = hw - h * WW;
            float oy = __ldg(goff + ((b * 2 * KK) + 2 * t) * HWSZ + hw);
            float ox = __ldg(goff + ((b * 2 * KK) + 2 * t + 1) * HWSZ + hw);
            float m = __ldg(gmask + (b * KK + t) * HWSZ + hw);
            int ty = t / K, tx = t - (t / K) * K;
            float py = (float)(h - P + ty) + oy;
            float px = (float)(w - P + tx) + ox;
            float y0f = floorf(py), x0f = floorf(px);
            float wy1 = py - y0f, wx1 = px - x0f;
            float wy0 = 1.f - wy1, wx0 = 1.f - wx1;
            float vy0 = (y0f >= 0.f && y0f <= (float)(HH - 1)) ? 1.f : 0.f;
            float vy1 = (y0f >= -1.f && y0f <= (float)(HH - 2)) ? 1.f : 0.f;
            float vx0 = (x0f >= 0.f && x0f <= (float)(WW - 1)) ? 1.f : 0.f;
            float vx1 = (x0f >= -1.f && x0f <= (float)(WW - 2)) ? 1.f : 0.f;
            int y0 = min(max((int)y0f, 0), HH - 1);
            int y1 = min(max((int)y0f + 1, 0), HH - 1);
            int x0 = min(max((int)x0f, 0), WW - 1);
            int x1 = min(max((int)x0f + 1, 0), WW - 1);
            sW[tid] = make_float4(wy0 * wx0 * vy0 * vx0 * m,
                                  wy0 * wx1 * vy0 * vx1 * m,
                                  wy1 * wx0 * vy1 * vx0 * m,
                                  wy1 * wx1 * vy1 * vx1 * m);
            sI[tid] = make_int4(y0 * WW + x0, y0 * WW + x1,
                                y1 * WW + x0, y1 * WW + x1);
        }
        __syncthreads();
        const float4 wv = sW[sp];
        const int4 iv = sI[sp];

        for (int cb = 0; cb < 64; cb += 16) {
            if (cb) __syncthreads();
            // stage weights [16 c][64 oc] from transposed layout (coalesced)
#pragma unroll
            for (int s = 0; s < 4; ++s) {
                int j = (tid >> 6) + 4 * s;
                int c = cb + j;
                Ws[j * AST + sp] = __ldg(wt + (t * 64 + c) * 64 + sp);
            }
            // stage sampled activations [16 c][64 p]
#pragma unroll
            for (int s = 0; s < 4; ++s) {
                int j = (tid >> 6) + 4 * s;
                int c = cb + j;
                const float* base = xb + c * HWSZ;
                float v = wv.x * __ldg(base + iv.x) + wv.y * __ldg(base + iv.y) +
                          wv.z * __ldg(base + iv.z) + wv.w * __ldg(base + iv.w);
                Bs[j * 64 + sp] = v;
            }
            __syncthreads();
#pragma unroll
            for (int j = 0; j < 16; ++j) {
                const float4 a = *(const float4*)(Ws + j * AST + oc0);
                const float4 bv = *(const float4*)(Bs + j * 64 + p0);
                acc[0][0] += a.x * bv.x; acc[0][1] += a.x * bv.y;
                acc[0][2] += a.x * bv.z; acc[0][3] += a.x * bv.w;
                acc[1][0] += a.y * bv.x; acc[1][1] += a.y * bv.y;
                acc[1][2] += a.y * bv.z; acc[1][3] += a.y * bv.w;
                acc[2][0] += a.z * bv.x; acc[2][1] += a.z * bv.y;
                acc[2][2] += a.z * bv.z; acc[2][3] += a.z * bv.w;
                acc[3][0] += a.w * bv.x; acc[3][1] += a.w * bv.y;
                acc[3][2] += a.w * bv.z; acc[3][3] += a.w * bv.w;
            }
        }
    }

    const int hw = pbase + p0;
#pragma unroll
    for (int i = 0; i < 4; ++i) {
        int oc = BROFF + oc0 + i;
        *(float4*)(out + (b * 192 + oc) * HWSZ + hw) =
            make_float4(acc[i][0], acc[i][1], acc[i][2], acc[i][3]);
    }
}

extern "C" void kernel_launch(void* const* d_in, const int* in_sizes, int n_in,
                              void* d_out, int out_size) {
    (void)in_sizes; (void)n_in; (void)out_size;
    const float* x       = (const float*)d_in[0];
    const float* w_off3  = (const float*)d_in[1];
    const float* b_off3  = (const float*)d_in[2];
    const float* w_mask3 = (const float*)d_in[3];
    const float* b_mask3 = (const float*)d_in[4];
    const float* w_dcn3  = (const float*)d_in[5];
    const float* w_off5  = (const float*)d_in[6];
    const float* b_off5  = (const float*)d_in[7];
    const float* w_mask5 = (const float*)d_in[8];
    const float* b_mask5 = (const float*)d_in[9];
    const float* w_dcn5  = (const float*)d_in[10];
    const float* w_off7  = (const float*)d_in[11];
    const float* b_off7  = (const float*)d_in[12];
    const float* w_mask7 = (const float*)d_in[13];
    const float* b_mask7 = (const float*)d_in[14];
    const float* w_dcn7  = (const float*)d_in[15];
    float* out = (float*)d_out;

    transpose_w<3><<<(9 * 4096 + 255) / 256, 256>>>(w_dcn3);
    transpose_w<5><<<(25 * 4096 + 255) / 256, 256>>>(w_dcn5);
    transpose_w<7><<<(49 * 4096 + 255) / 256, 256>>>(w_dcn7);

    conv_offmask<3><<<dim3(100, 1, NB), 256>>>(x, w_off3, b_off3, w_mask3, b_mask3);
    conv_offmask<5><<<dim3(100, 3, NB), 256>>>(x, w_off5, b_off5, w_mask5, b_mask5);
    conv_offmask<7><<<dim3(100, 5, NB), 256>>>(x, w_off7, b_off7, w_mask7, b_mask7);

    deform_gemm<3, 0><<<dim3(100, NB), 256>>>(x, out);
    deform_gemm<5, 64><<<dim3(100, NB), 256>>>(x, out);
    deform_gemm<7, 128><<<dim3(100, NB), 256>>>(x, out);
}

// round 2
// speedup vs baseline: 1.1055x; 1.1055x over previous
#include <cuda_runtime.h>

#define HH 80
#define WW 80
#define HWSZ 6400
#define NB 2
#define CI 64

// ---------------- scratch (__device__ globals; no allocation) ----------------
__device__ float g_off3[NB * 18 * HWSZ];
__device__ float g_mask3[NB * 9 * HWSZ];
__device__ float g_off5[NB * 50 * HWSZ];
__device__ float g_mask5[NB * 25 * HWSZ];
__device__ float g_off7[NB * 98 * HWSZ];
__device__ float g_mask7[NB * 49 * HWSZ];
__device__ float g_wt3[9 * 64 * 64];    // [t][c][oc]
__device__ float g_wt5[25 * 64 * 64];
__device__ float g_wt7[49 * 64 * 64];

template <int K> __device__ __forceinline__ float* off_buf() {
    if constexpr (K == 3) return g_off3;
    else if constexpr (K == 5) return g_off5;
    else return g_off7;
}
template <int K> __device__ __forceinline__ float* mask_buf() {
    if constexpr (K == 3) return g_mask3;
    else if constexpr (K == 5) return g_mask5;
    else return g_mask7;
}
template <int K> __device__ __forceinline__ float* wt_buf() {
    if constexpr (K == 3) return g_wt3;
    else if constexpr (K == 5) return g_wt5;
    else return g_wt7;
}

// ---------------- fused transpose of all w_dcn (OC,C,k,k) -> (t,c,oc) --------
__global__ __launch_bounds__(256) void transpose_all(
    const float* __restrict__ w3, const float* __restrict__ w5,
    const float* __restrict__ w7) {
    int idx = blockIdx.x * 256 + threadIdx.x;
    const float* w;
    float* dst;
    int kk;
    if (idx < 9 * 4096) { w = w3; dst = g_wt3; kk = 9; }
    else if (idx < (9 + 25) * 4096) { idx -= 9 * 4096; w = w5; dst = g_wt5; kk = 25; }
    else if (idx < (9 + 25 + 49) * 4096) { idx -= (9 + 25) * 4096; w = w7; dst = g_wt7; kk = 49; }
    else return;
    int oc = idx & 63;
    int rem = idx >> 6;
    int c = rem & 63;
    int t = rem >> 6;
    dst[idx] = w[(oc * 64 + c) * kk + t];
}

// ---------------- fused offset+mask conv branch (implicit GEMM) --------------
// 256 threads, 64 pixels x 32 output channels, double-buffered 16-deep chunks.
template <int K>
__device__ __forceinline__ void conv_branch(
    const float* __restrict__ x,
    const float* __restrict__ w_off, const float* __restrict__ b_off,
    const float* __restrict__ w_mask, const float* __restrict__ b_mask,
    float* As, float* Bs, int ocbase, int b, int pbase) {
    constexpr int KK = K * K;
    constexpr int OC = 3 * KK;
    constexpr int P = K / 2;
    constexpr int R = CI * KK;
    constexpr int NCH = R / 16;
    constexpr int AST = 36;

    const int tid = threadIdx.x;
    const int sp = tid & 63;
    const int shw = pbase + sp;
    const int sh = shw / WW;
    const int sw = shw - sh * WW;
    const float* xb = x + b * CI * HWSZ;

    const int oc0 = (tid >> 4) * 2;
    const int p0 = (tid & 15) * 4;
    const int aj = tid & 15;
    const int ai = tid >> 4;

    float acc[2][4];
#pragma unroll
    for (int i = 0; i < 2; ++i)
#pragma unroll
        for (int l = 0; l < 4; ++l) acc[i][l] = 0.f;

    auto stage = [&](int n, int buf) {
        float* Asb = As + buf * 16 * AST;
        float* Bsb = Bs + buf * 16 * 64;
        const int rbase = n * 16;
#pragma unroll
        for (int s = 0; s < 4; ++s) {
            int j = (tid >> 6) + 4 * s;
            int r = rbase + j;
            int ci = r / KK;
            int t = r - ci * KK;
            int ky = t / K;
            int kx = t - ky * K;
            int y = sh + ky - P;
            int xx = sw + kx - P;
            float v = 0.f;
            if (y >= 0 && y < HH && xx >= 0 && xx < WW)
                v = __ldg(xb + ci * HWSZ + y * WW + xx);
            Bsb[j * 64 + sp] = v;
        }
#pragma unroll
        for (int s = 0; s < 2; ++s) {
            int i = ai + 16 * s;
            int r = rbase + aj;
            int oc = ocbase + i;
            float v = 0.f;
            if (oc < 2 * KK) v = __ldg(w_off + oc * R + r);
            else if (oc < OC) v = __ldg(w_mask + (oc - 2 * KK) * R + r);
            Asb[aj * AST + i] = v;
        }
    };

    stage(0, 0);
    __syncthreads();
    for (int n = 0; n < NCH; ++n) {
        if (n + 1 < NCH) stage(n + 1, (n + 1) & 1);
        const float* Asb = As + (n & 1) * 16 * AST;
        const float* Bsb = Bs + (n & 1) * 16 * 64;
#pragma unroll
        for (int j = 0; j < 16; ++j) {
            const float2 a = *(const float2*)(Asb + j * AST + oc0);
            const float4 bv = *(const float4*)(Bsb + j * 64 + p0);
            acc[0][0] += a.x * bv.x; acc[0][1] += a.x * bv.y;
            acc[0][2] += a.x * bv.z; acc[0][3] += a.x * bv.w;
            acc[1][0] += a.y * bv.x; acc[1][1] += a.y * bv.y;
            acc[1][2] += a.y * bv.z; acc[1][3] += a.y * bv.w;
        }
        __syncthreads();
    }

    const int hw = pbase + p0;
#pragma unroll
    for (int i = 0; i < 2; ++i) {
        int oc = ocbase + oc0 + i;
        if (oc >= OC) continue;
        if (oc < 2 * KK) {
            float bias = __ldg(b_off + oc);
            float4 v = make_float4(acc[i][0] + bias, acc[i][1] + bias,
                                   acc[i][2] + bias, acc[i][3] + bias);
            *(float4*)(off_buf<K>() + (b * 2 * KK + oc) * HWSZ + hw) = v;
        } else {
            float bias = __ldg(b_mask + (oc - 2 * KK));
            float4 v;
            v.x = 1.f / (1.f + __expf(-(acc[i][0] + bias)));
            v.y = 1.f / (1.f + __expf(-(acc[i][1] + bias)));
            v.z = 1.f / (1.f + __expf(-(acc[i][2] + bias)));
            v.w = 1.f / (1.f + __expf(-(acc[i][3] + bias)));
            *(float4*)(mask_buf<K>() + (b * KK + (oc - 2 * KK)) * HWSZ + hw) = v;
        }
    }
}

__global__ __launch_bounds__(256) void conv_fused(
    const float* __restrict__ x,
    const float* __restrict__ w_off3, const float* __restrict__ b_off3,
    const float* __restrict__ w_mask3, const float* __restrict__ b_mask3,
    const float* __restrict__ w_off5, const float* __restrict__ b_off5,
    const float* __restrict__ w_mask5, const float* __restrict__ b_mask5,
    const float* __restrict__ w_off7, const float* __restrict__ b_off7,
    const float* __restrict__ w_mask7, const float* __restrict__ b_mask7) {
    __shared__ float As[2 * 16 * 36];
    __shared__ float Bs[2 * 16 * 64];
    const int yb = blockIdx.y;
    const int b = blockIdx.z;
    const int pbase = blockIdx.x * 64;
    if (yb == 0)
        conv_branch<3>(x, w_off3, b_off3, w_mask3, b_mask3, As, Bs, 0, b, pbase);
    else if (yb < 4)
        conv_branch<5>(x, w_off5, b_off5, w_mask5, b_mask5, As, Bs, (yb - 1) * 32, b, pbase);
    else
        conv_branch<7>(x, w_off7, b_off7, w_mask7, b_mask7, As, Bs, (yb - 4) * 32, b, pbase);
}

// ---------------- fused deformable sampling + GEMM ---------------------------
// 256 threads, 64 pixels x 64 output channels, double-buffered, register
// bilinear descriptors with 1-tap-ahead raw prefetch.
template <int K, int BROFF>
__device__ __forceinline__ void deform_branch(
    const float* __restrict__ x, float* __restrict__ out,
    float* Ws, float* Bs, int b, int pbase) {
    constexpr int KK = K * K;
    constexpr int P = K / 2;
    constexpr int WST = 68;
    constexpr int NCH = KK * 4;

    const int tid = threadIdx.x;
    const int sp = tid & 63;
    const int shw = pbase + sp;
    const int sh = shw / WW;
    const int swp = shw - sh * WW;
    const float* xb = x + b * CI * HWSZ;
    const float* wt = wt_buf<K>();
    const float* goff = off_buf<K>();
    const float* gmask = mask_buf<K>();

    const int oc0 = (tid >> 4) * 4;
    const int p0 = (tid & 15) * 4;

    float r_oy, r_ox, r_m;       // prefetched raw offset/mask for next tap
    float4 dw;                   // bilinear weights * mask
    int4 di;                     // gather indices

    auto prefetch_raw = [&](int t) {
        if (t < KK) {
            r_oy = __ldg(goff + (b * 2 * KK + 2 * t) * HWSZ + shw);
            r_ox = __ldg(goff + (b * 2 * KK + 2 * t + 1) * HWSZ + shw);
            r_m = __ldg(gmask + (b * KK + t) * HWSZ + shw);
        }
    };
    auto finalize_desc = [&](int t) {
        int ty = t / K, tx = t - ty * K;
        float py = (float)(sh - P + ty) + r_oy;
        float px = (float)(swp - P + tx) + r_ox;
        float y0f = floorf(py), x0f = floorf(px);
        float wy1 = py - y0f, wx1 = px - x0f;
        float wy0 = 1.f - wy1, wx0 = 1.f - wx1;
        float vy0 = (y0f >= 0.f && y0f <= (float)(HH - 1)) ? 1.f : 0.f;
        float vy1 = (y0f >= -1.f && y0f <= (float)(HH - 2)) ? 1.f : 0.f;
        float vx0 = (x0f >= 0.f && x0f <= (float)(WW - 1)) ? 1.f : 0.f;
        float vx1 = (x0f >= -1.f && x0f <= (float)(WW - 2)) ? 1.f : 0.f;
        int y0 = min(max((int)y0f, 0), HH - 1);
        int y1 = min(max((int)y0f + 1, 0), HH - 1);
        int x0 = min(max((int)x0f, 0), WW - 1);
        int x1 = min(max((int)x0f + 1, 0), WW - 1);
        dw = make_float4(wy0 * wx0 * vy0 * vx0 * r_m,
                         wy0 * wx1 * vy0 * vx1 * r_m,
                         wy1 * wx0 * vy1 * vx0 * r_m,
                         wy1 * wx1 * vy1 * vx1 * r_m);
        di = make_int4(y0 * WW + x0, y0 * WW + x1, y1 * WW + x0, y1 * WW + x1);
    };

    auto stage = [&](int n, int buf) {
        const int t = n >> 2;
        const int cb = (n & 3) * 16;
        if ((n & 3) == 0) {
            finalize_desc(t);
            prefetch_raw(t + 1);
        }
        float* Wsb = Ws + buf * 16 * WST;
        float* Bsb = Bs + buf * 16 * 64;
#pragma unroll
        for (int s = 0; s < 4; ++s) {
            int j = (tid >> 6) + 4 * s;
            int c = cb + j;
            Wsb[j * WST + sp] = __ldg(wt + (t * 64 + c) * 64 + sp);
            const float* base = xb + c * HWSZ;
            float v = dw.x * __ldg(base + di.x) + dw.y * __ldg(base + di.y) +
                      dw.z * __ldg(base + di.z) + dw.w * __ldg(base + di.w);
            Bsb[j * 64 + sp] = v;
        }
    };

    float acc[4][4];
#pragma unroll
    for (int i = 0; i < 4; ++i)
#pragma unroll
        for (int l = 0; l < 4; ++l) acc[i][l] = 0.f;

    prefetch_raw(0);
    stage(0, 0);
    __syncthreads();
    for (int n = 0; n < NCH; ++n) {
        if (n + 1 < NCH) stage(n + 1, (n + 1) & 1);
        const float* Wsb = Ws + (n & 1) * 16 * WST;
        const float* Bsb = Bs + (n & 1) * 16 * 64;
#pragma unroll
        for (int j = 0; j < 16; ++j) {
            const float4 a = *(const float4*)(Wsb + j * WST + oc0);
            const float4 bv = *(const float4*)(Bsb + j * 64 + p0);
            acc[0][0] += a.x * bv.x; acc[0][1] += a.x * bv.y;
            acc[0][2] += a.x * bv.z; acc[0][3] += a.x * bv.w;
            acc[1][0] += a.y * bv.x; acc[1][1] += a.y * bv.y;
            acc[1][2] += a.y * bv.z; acc[1][3] += a.y * bv.w;
            acc[2][0] += a.z * bv.x; acc[2][1] += a.z * bv.y;
            acc[2][2] += a.z * bv.z; acc[2][3] += a.z * bv.w;
            acc[3][0] += a.w * bv.x; acc[3][1] += a.w * bv.y;
            acc[3][2] += a.w * bv.z; acc[3][3] += a.w * bv.w;
        }
        __syncthreads();
    }

    const int hw = pbase + p0;
#pragma unroll
    for (int i = 0; i < 4; ++i) {
        int oc = BROFF + oc0 + i;
        *(float4*)(out + (b * 192 + oc) * HWSZ + hw) =
            make_float4(acc[i][0], acc[i][1], acc[i][2], acc[i][3]);
    }
}

__global__ __launch_bounds__(256) void deform_fused(
    const float* __restrict__ x, float* __restrict__ out) {
    __shared__ float Ws[2 * 16 * 68];
    __shared__ float Bs[2 * 16 * 64];
    const int br = blockIdx.y;
    const int b = blockIdx.z;
    const int pbase = blockIdx.x * 64;
    if (br == 0) deform_branch<3, 0>(x, out, Ws, Bs, b, pbase);
    else if (br == 1) deform_branch<5, 64>(x, out, Ws, Bs, b, pbase);
    else deform_branch<7, 128>(x, out, Ws, Bs, b, pbase);
}

extern "C" void kernel_launch(void* const* d_in, const int* in_sizes, int n_in,
                              void* d_out, int out_size) {
    (void)in_sizes; (void)n_in; (void)out_size;
    const float* x       = (const float*)d_in[0];
    const float* w_off3  = (const float*)d_in[1];
    const float* b_off3  = (const float*)d_in[2];
    const float* w_mask3 = (const float*)d_in[3];
    const float* b_mask3 = (const float*)d_in[4];
    const float* w_dcn3  = (const float*)d_in[5];
    const float* w_off5  = (const float*)d_in[6];
    const float* b_off5  = (const float*)d_in[7];
    const float* w_mask5 = (const float*)d_in[8];
    const float* b_mask5 = (const float*)d_in[9];
    const float* w_dcn5  = (const float*)d_in[10];
    const float* w_off7  = (const float*)d_in[11];
    const float* b_off7  = (const float*)d_in[12];
    const float* w_mask7 = (const float*)d_in[13];
    const float* b_mask7 = (const float*)d_in[14];
    const float* w_dcn7  = (const float*)d_in[15];
    float* out = (float*)d_out;

    transpose_all<<<(83 * 4096 + 255) / 256, 256>>>(w_dcn3, w_dcn5, w_dcn7);

    conv_fused<<<dim3(100, 9, NB), 256>>>(
        x, w_off3, b_off3, w_mask3, b_mask3,
        w_off5, b_off5, w_mask5, b_mask5,
        w_off7, b_off7, w_mask7, b_mask7);

    deform_fused<<<dim3(100, 3, NB), 256>>>(x, out);
}

// round 4
// speedup vs baseline: 1.7785x; 1.6087x over previous
#include <cuda_runtime.h>
#include <cstdint>

#define HH 80
#define WW 80
#define HWSZ 6400
#define NB 2
#define CI 64

// ---------------- scratch (__device__ globals; no allocation) ----------------
__device__ float g_off3[NB * 18 * HWSZ];
__device__ float g_mask3[NB * 9 * HWSZ];
__device__ float g_off5[NB * 50 * HWSZ];
__device__ float g_mask5[NB * 25 * HWSZ];
__device__ float g_off7[NB * 98 * HWSZ];
__device__ float g_mask7[NB * 49 * HWSZ];
__device__ float g_wt3[9 * 64 * 64];    // [t][c][oc], tf32-rounded
__device__ float g_wt5[25 * 64 * 64];
__device__ float g_wt7[49 * 64 * 64];

template <int K> __device__ __forceinline__ float* off_buf() {
    if constexpr (K == 3) return g_off3;
    else if constexpr (K == 5) return g_off5;
    else return g_off7;
}
template <int K> __device__ __forceinline__ float* mask_buf() {
    if constexpr (K == 3) return g_mask3;
    else if constexpr (K == 5) return g_mask5;
    else return g_mask7;
}
template <int K> __device__ __forceinline__ float* wt_buf() {
    if constexpr (K == 3) return g_wt3;
    else if constexpr (K == 5) return g_wt5;
    else return g_wt7;
}

// ---------------- tf32 helpers ----------------
__device__ __forceinline__ uint32_t f2tf(float x) {
    uint32_t u;
    asm("cvt.rna.tf32.f32 %0, %1;" : "=r"(u) : "f"(x));
    return u;
}
__device__ __forceinline__ float f2tff(float x) { return __uint_as_float(f2tf(x)); }

__device__ __forceinline__ void mma8(float c[4], uint32_t a0, uint32_t a1,
                                     uint32_t a2, uint32_t a3,
                                     uint32_t b0, uint32_t b1) {
    asm volatile(
        "mma.sync.aligned.m16n8k8.row.col.f32.tf32.tf32.f32 "
        "{%0,%1,%2,%3},{%4,%5,%6,%7},{%8,%9},{%0,%1,%2,%3};"
        : "+f"(c[0]), "+f"(c[1]), "+f"(c[2]), "+f"(c[3])
        : "r"(a0), "r"(a1), "r"(a2), "r"(a3), "r"(b0), "r"(b1));
}

// A: k-major [k][m], stride AST; B: n-major [n][k16], stride 20.
// Warp computes m16 x n32 (4 n8-tiles) over k16.
template <int AST>
__device__ __forceinline__ void mma_chunk(const float* __restrict__ A,
                                          const float* __restrict__ B,
                                          int mbase, int nbase, int g, int tg,
                                          float acc[4][4]) {
#pragma unroll
    for (int ks = 0; ks < 16; ks += 8) {
        uint32_t a0 = __float_as_uint(A[(ks + tg) * AST + mbase + g]);
        uint32_t a1 = __float_as_uint(A[(ks + tg) * AST + mbase + g + 8]);
        uint32_t a2 = __float_as_uint(A[(ks + tg + 4) * AST + mbase + g]);
        uint32_t a3 = __float_as_uint(A[(ks + tg + 4) * AST + mbase + g + 8]);
#pragma unroll
        for (int nt = 0; nt < 4; ++nt) {
            const float* bp = B + (nbase + nt * 8 + g) * 20 + ks + tg;
            mma8(acc[nt], a0, a1, a2, a3,
                 __float_as_uint(bp[0]), __float_as_uint(bp[4]));
        }
    }
}

// ---------------- transpose + tf32-round all w_dcn -> (t,c,oc) ---------------
__global__ __launch_bounds__(256) void transpose_all(
    const float* __restrict__ w3, const float* __restrict__ w5,
    const float* __restrict__ w7) {
    int idx = blockIdx.x * 256 + threadIdx.x;
    const float* w;
    float* dst;
    int kk;
    if (idx < 9 * 4096) { w = w3; dst = g_wt3; kk = 9; }
    else if (idx < (9 + 25) * 4096) { idx -= 9 * 4096; w = w5; dst = g_wt5; kk = 25; }
    else if (idx < (9 + 25 + 49) * 4096) { idx -= (9 + 25) * 4096; w = w7; dst = g_wt7; kk = 49; }
    else return;
    int oc = idx & 63;
    int rem = idx >> 6;
    int c = rem & 63;
    int t = rem >> 6;
    dst[idx] = f2tff(w[(oc * 64 + c) * kk + t]);
}

// ---------------- conv phase: 32 oc x 128 pix per CTA, mma tf32 --------------
template <int K>
__device__ __forceinline__ void conv_branch(
    const float* __restrict__ x,
    const float* __restrict__ w_off, const float* __restrict__ b_off,
    const float* __restrict__ w_mask, const float* __restrict__ b_mask,
    float* As, float* Bs, int ocbase, int b, int pbase) {
    constexpr int KK = K * K;
    constexpr int P = K / 2;
    constexpr int R = CI * KK;
    constexpr int NCH = R / 16;
    constexpr int AST = 40;

    const int tid = threadIdx.x;
    const int wid = tid >> 5;
    const int lane = tid & 31;
    const int g = lane >> 2;
    const int tg = lane & 3;
    const int mbase = (wid & 1) * 16;
    const int nbase = (wid >> 1) * 32;

    // staging ids
    const int aoc = tid & 31;
    const int akp = tid >> 5;          // 0..7, 2 k each
    const int bpix = tid & 127;
    const int bkh = (tid >> 7) * 8;    // 0 or 8
    const int phw = pbase + bpix;
    const int ph = phw / WW;
    const int pw = phw - ph * WW;
    const float* xb = x + b * CI * HWSZ;

    const int ocg = ocbase + aoc;
    const float* arow = w_off;
    bool areal = true;
    if (ocg < 2 * KK) arow = w_off + ocg * R;
    else if (ocg < 3 * KK) arow = w_mask + (ocg - 2 * KK) * R;
    else areal = false;

    auto stage = [&](int n, int buf) {
        const int rbase = n * 16;
        float* Ab = As + buf * 16 * AST;
        float* Bb = Bs + buf * 128 * 20;
        float2 av = make_float2(0.f, 0.f);
        if (areal) av = *(const float2*)(arow + rbase + akp * 2);
        Ab[(akp * 2 + 0) * AST + aoc] = f2tff(av.x);
        Ab[(akp * 2 + 1) * AST + aoc] = f2tff(av.y);
        float bv[8];
#pragma unroll
        for (int j = 0; j < 8; ++j) {
            int k = rbase + bkh + j;
            int ci = k / KK;
            int t = k - ci * KK;
            int ky = t / K;
            int kx = t - ky * K;
            int y = ph + ky - P;
            int xx = pw + kx - P;
            bv[j] = 0.f;
            if (y >= 0 && y < HH && xx >= 0 && xx < WW)
                bv[j] = f2tff(__ldg(xb + ci * HWSZ + y * WW + xx));
        }
        *(float4*)(Bb + bpix * 20 + bkh) = make_float4(bv[0], bv[1], bv[2], bv[3]);
        *(float4*)(Bb + bpix * 20 + bkh + 4) = make_float4(bv[4], bv[5], bv[6], bv[7]);
    };

    float acc[4][4];
#pragma unroll
    for (int i = 0; i < 4; ++i)
#pragma unroll
        for (int l = 0; l < 4; ++l) acc[i][l] = 0.f;

    stage(0, 0);
    __syncthreads();
    for (int n = 0; n < NCH; ++n) {
        if (n + 1 < NCH) stage(n + 1, (n + 1) & 1);
        mma_chunk<AST>(As + (n & 1) * 16 * AST, Bs + (n & 1) * 128 * 20,
                       mbase, nbase, g, tg, acc);
        __syncthreads();
    }

    // epilogue
#pragma unroll
    for (int r = 0; r < 2; ++r) {
        int ocl = ocbase + mbase + g + r * 8;
        float* dst;
        float bias;
        bool msk;
        if (ocl < 2 * KK) {
            dst = off_buf<K>() + ((size_t)(b * 2 * KK + ocl)) * HWSZ;
            bias = __ldg(b_off + ocl);
            msk = false;
        } else if (ocl < 3 * KK) {
            dst = mask_buf<K>() + ((size_t)(b * KK + (ocl - 2 * KK))) * HWSZ;
            bias = __ldg(b_mask + (ocl - 2 * KK));
            msk = true;
        } else continue;
#pragma unroll
        for (int nt = 0; nt < 4; ++nt) {
            int col = pbase + nbase + nt * 8 + tg * 2;
            float f0 = acc[nt][r * 2] + bias;
            float f1 = acc[nt][r * 2 + 1] + bias;
            if (msk) {
                f0 = 1.f / (1.f + __expf(-f0));
                f1 = 1.f / (1.f + __expf(-f1));
            }
            *(float2*)(dst + col) = make_float2(f0, f1);
        }
    }
}

__global__ __launch_bounds__(256) void conv_tc(
    const float* __restrict__ x,
    const float* __restrict__ w_off3, const float* __restrict__ b_off3,
    const float* __restrict__ w_mask3, const float* __restrict__ b_mask3,
    const float* __restrict__ w_off5, const float* __restrict__ b_off5,
    const float* __restrict__ w_mask5, const float* __restrict__ b_mask5,
    const float* __restrict__ w_off7, const float* __restrict__ b_off7,
    const float* __restrict__ w_mask7, const float* __restrict__ b_mask7) {
    __shared__ float As[2 * 16 * 40];
    __shared__ float Bs[2 * 128 * 20];
    const int yb = blockIdx.y;
    const int b = blockIdx.z;
    const int pbase = blockIdx.x * 128;
    if (yb == 0)
        conv_branch<3>(x, w_off3, b_off3, w_mask3, b_mask3, As, Bs, 0, b, pbase);
    else if (yb < 4)
        conv_branch<5>(x, w_off5, b_off5, w_mask5, b_mask5, As, Bs, (yb - 1) * 32, b, pbase);
    else
        conv_branch<7>(x, w_off7, b_off7, w_mask7, b_mask7, As, Bs, (yb - 4) * 32, b, pbase);
}

// ---------------- deform phase: 64 oc x 64 pix per CTA, mma tf32 -------------
template <int K, int BROFF>
__device__ __forceinline__ void deform_branch(
    const float* __restrict__ x, float* __restrict__ out,
    float* As, float* Bs, int b, int pbase) {
    constexpr int KK = K * K;
    constexpr int P = K / 2;
    constexpr int NCH = KK * 4;
    constexpr int AST = 72;

    const int tid = threadIdx.x;
    const int wid = tid >> 5;
    const int lane = tid & 31;
    const int g = lane >> 2;
    const int tg = lane & 3;
    const int mbase = (wid & 3) * 16;
    const int nbase = (wid >> 2) * 32;

    const int sp = tid & 63;           // staging pixel (B) / oc (A)
    const int cg = tid >> 6;           // 0..3, 4 c each
    const int shw = pbase + sp;
    const int sh = shw / WW;
    const int swp = shw - sh * WW;
    const float* xb = x + b * CI * HWSZ;
    const float* wt = wt_buf<K>();
    const float* goff = off_buf<K>();
    const float* gmask = mask_buf<K>();

    float r_oy, r_ox, r_m;
    float4 dw;
    int4 di;

    auto prefetch_raw = [&](int t) {
        if (t < KK) {
            r_oy = __ldg(goff + (b * 2 * KK + 2 * t) * HWSZ + shw);
            r_ox = __ldg(goff + (b * 2 * KK + 2 * t + 1) * HWSZ + shw);
            r_m = __ldg(gmask + (b * KK + t) * HWSZ + shw);
        }
    };
    auto finalize_desc = [&](int t) {
        int ty = t / K, tx = t - ty * K;
        float py = (float)(sh - P + ty) + r_oy;
        float px = (float)(swp - P + tx) + r_ox;
        float y0f = floorf(py), x0f = floorf(px);
        float wy1 = py - y0f, wx1 = px - x0f;
        float wy0 = 1.f - wy1, wx0 = 1.f - wx1;
        float vy0 = (y0f >= 0.f && y0f <= (float)(HH - 1)) ? 1.f : 0.f;
        float vy1 = (y0f >= -1.f && y0f <= (float)(HH - 2)) ? 1.f : 0.f;
        float vx0 = (x0f >= 0.f && x0f <= (float)(WW - 1)) ? 1.f : 0.f;
        float vx1 = (x0f >= -1.f && x0f <= (float)(WW - 2)) ? 1.f : 0.f;
        int y0 = min(max((int)y0f, 0), HH - 1);
        int y1 = min(max((int)y0f + 1, 0), HH - 1);
        int x0 = min(max((int)x0f, 0), WW - 1);
        int x1 = min(max((int)x0f + 1, 0), WW - 1);
        dw = make_float4(wy0 * wx0 * vy0 * vx0 * r_m,
                         wy0 * wx1 * vy0 * vx1 * r_m,
                         wy1 * wx0 * vy1 * vx0 * r_m,
                         wy1 * wx1 * vy1 * vx1 * r_m);
        di = make_int4(y0 * WW + x0, y0 * WW + x1, y1 * WW + x0, y1 * WW + x1);
    };

    auto stage = [&](int n, int buf) {
        const int t = n >> 2;
        const int cb = (n & 3) * 16;
        if ((n & 3) == 0) {
            finalize_desc(t);
            prefetch_raw(t + 1);
        }
        float* Ab = As + buf * 16 * AST;
        float* Bb = Bs + buf * 64 * 20;
        // A: weights [16 c][64 oc], k-major; this thread: oc=sp, c = cb+cg*4+i
        float bv[4];
#pragma unroll
        for (int i = 0; i < 4; ++i) {
            int cc = cb + cg * 4 + i;
            Ab[(cg * 4 + i) * AST + sp] = __ldg(wt + (t * 64 + cc) * 64 + sp);
            const float* base = xb + cc * HWSZ;
            float v = dw.x * __ldg(base + di.x) + dw.y * __ldg(base + di.y) +
                      dw.z * __ldg(base + di.z) + dw.w * __ldg(base + di.w);
            bv[i] = f2tff(v);
        }
        *(float4*)(Bb + sp * 20 + cg * 4) = make_float4(bv[0], bv[1], bv[2], bv[3]);
    };

    float acc[4][4];
#pragma unroll
    for (int i = 0; i < 4; ++i)
#pragma unroll
        for (int l = 0; l < 4; ++l) acc[i][l] = 0.f;

    prefetch_raw(0);
    stage(0, 0);
    __syncthreads();
    for (int n = 0; n < NCH; ++n) {
        if (n + 1 < NCH) stage(n + 1, (n + 1) & 1);
        mma_chunk<AST>(As + (n & 1) * 16 * AST, Bs + (n & 1) * 64 * 20,
                       mbase, nbase, g, tg, acc);
        __syncthreads();
    }

#pragma unroll
    for (int r = 0; r < 2; ++r) {
        int ocl = BROFF + mbase + g + r * 8;
        float* dst = out + ((size_t)(b * 192 + ocl)) * HWSZ;
#pragma unroll
        for (int nt = 0; nt < 4; ++nt) {
            int col = pbase + nbase + nt * 8 + tg * 2;
            *(float2*)(dst + col) = make_float2(acc[nt][r * 2], acc[nt][r * 2 + 1]);
        }
    }
}

__global__ __launch_bounds__(256) void deform_tc(
    const float* __restrict__ x, float* __restrict__ out) {
    __shared__ float As[2 * 16 * 72];
    __shared__ float Bs[2 * 64 * 20];
    const int br = blockIdx.y;
    const int b = blockIdx.z;
    const int pbase = blockIdx.x * 64;
    if (br == 0) deform_branch<3, 0>(x, out, As, Bs, b, pbase);
    else if (br == 1) deform_branch<5, 64>(x, out, As, Bs, b, pbase);
    else deform_branch<7, 128>(x, out, As, Bs, b, pbase);
}

extern "C" void kernel_launch(void* const* d_in, const int* in_sizes, int n_in,
                              void* d_out, int out_size) {
    (void)in_sizes; (void)n_in; (void)out_size;
    const float* x       = (const float*)d_in[0];
    const float* w_off3  = (const float*)d_in[1];
    const float* b_off3  = (const float*)d_in[2];
    const float* w_mask3 = (const float*)d_in[3];
    const float* b_mask3 = (const float*)d_in[4];
    const float* w_dcn3  = (const float*)d_in[5];
    const float* w_off5  = (const float*)d_in[6];
    const float* b_off5  = (const float*)d_in[7];
    const float* w_mask5 = (const float*)d_in[8];
    const float* b_mask5 = (const float*)d_in[9];
    const float* w_dcn5  = (const float*)d_in[10];
    const float* w_off7  = (const float*)d_in[11];
    const float* b_off7  = (const float*)d_in[12];
    const float* w_mask7 = (const float*)d_in[13];
    const float* b_mask7 = (const float*)d_in[14];
    const float* w_dcn7  = (const float*)d_in[15];
    float* out = (float*)d_out;

    transpose_all<<<(83 * 4096 + 255) / 256, 256>>>(w_dcn3, w_dcn5, w_dcn7);

    conv_tc<<<dim3(50, 9, NB), 256>>>(
        x, w_off3, b_off3, w_mask3, b_mask3,
        w_off5, b_off5, w_mask5, b_mask5,
        w_off7, b_off7, w_mask7, b_mask7);

    deform_tc<<<dim3(100, 3, NB), 256>>>(x, out);
}

// round 5
// speedup vs baseline: 2.3978x; 1.3482x over previous
#include <cuda_runtime.h>
#include <cstdint>

#define HH 80
#define WW 80
#define HWSZ 6400
#define NB 2
#define CI 64
#define PH 86
#define PHW2 7396   // 86*86

// ---------------- scratch (__device__ globals; no allocation) ----------------
__device__ float g_off3[NB * 18 * HWSZ];
__device__ float g_mask3[NB * 9 * HWSZ];
__device__ float g_off5[NB * 50 * HWSZ];
__device__ float g_mask5[NB * 25 * HWSZ];
__device__ float g_off7[NB * 98 * HWSZ];
__device__ float g_mask7[NB * 49 * HWSZ];
__device__ float g_wt3[9 * 64 * 64];    // [t][c][oc], tf32-rounded (deform A)
__device__ float g_wt5[25 * 64 * 64];
__device__ float g_wt7[49 * 64 * 64];
__device__ float g_wa3[576 * 32];       // conv A: [k=(t,c)][ocpad], tf32
__device__ float g_wa5[1600 * 96];
__device__ float g_wa7[3136 * 160];
__device__ float g_xpad[NB * CI * PHW2];  // padded + tf32-rounded image

template <int K> __device__ __forceinline__ float* off_buf() {
    if constexpr (K == 3) return g_off3;
    else if constexpr (K == 5) return g_off5;
    else return g_off7;
}
template <int K> __device__ __forceinline__ float* mask_buf() {
    if constexpr (K == 3) return g_mask3;
    else if constexpr (K == 5) return g_mask5;
    else return g_mask7;
}
template <int K> __device__ __forceinline__ float* wt_buf() {
    if constexpr (K == 3) return g_wt3;
    else if constexpr (K == 5) return g_wt5;
    else return g_wt7;
}
template <int K> __device__ __forceinline__ float* wa_buf() {
    if constexpr (K == 3) return g_wa3;
    else if constexpr (K == 5) return g_wa5;
    else return g_wa7;
}

// ---------------- tf32 helpers ----------------
__device__ __forceinline__ uint32_t f2tf(float x) {
    uint32_t u;
    asm("cvt.rna.tf32.f32 %0, %1;" : "=r"(u) : "f"(x));
    return u;
}
__device__ __forceinline__ float f2tff(float x) { return __uint_as_float(f2tf(x)); }

__device__ __forceinline__ void mma8(float c[4], uint32_t a0, uint32_t a1,
                                     uint32_t a2, uint32_t a3,
                                     uint32_t b0, uint32_t b1) {
    asm volatile(
        "mma.sync.aligned.m16n8k8.row.col.f32.tf32.tf32.f32 "
        "{%0,%1,%2,%3},{%4,%5,%6,%7},{%8,%9},{%0,%1,%2,%3};"
        : "+f"(c[0]), "+f"(c[1]), "+f"(c[2]), "+f"(c[3])
        : "r"(a0), "r"(a1), "r"(a2), "r"(a3), "r"(b0), "r"(b1));
}

// A: k-major [k][m] stride AST; B: n-major [n][k] stride BST. 32-deep chunk.
template <int AST, int BST>
__device__ __forceinline__ void mma_chunk32(const float* __restrict__ A,
                                            const float* __restrict__ B,
                                            int mbase, int nbase, int g, int tg,
                                            float acc[4][4]) {
#pragma unroll
    for (int ks = 0; ks < 32; ks += 8) {
        uint32_t a0 = __float_as_uint(A[(ks + tg) * AST + mbase + g]);
        uint32_t a1 = __float_as_uint(A[(ks + tg) * AST + mbase + g + 8]);
        uint32_t a2 = __float_as_uint(A[(ks + tg + 4) * AST + mbase + g]);
        uint32_t a3 = __float_as_uint(A[(ks + tg + 4) * AST + mbase + g + 8]);
#pragma unroll
        for (int nt = 0; nt < 4; ++nt) {
            const float* bp = B + (nbase + nt * 8 + g) * BST + ks + tg;
            mma8(acc[nt], a0, a1, a2, a3,
                 __float_as_uint(bp[0]), __float_as_uint(bp[4]));
        }
    }
}

// ---------------- single prep kernel: wt transpose, conv-A prep, xpad --------
#define S_WT 339968          // (9+25+49)*4096
#define S_WA 673792          // 576*32 + 1600*96 + 3136*160
#define S_XP (NB * CI * PHW2)
__global__ __launch_bounds__(256) void prep_all(
    const float* __restrict__ x,
    const float* __restrict__ wd3, const float* __restrict__ wd5,
    const float* __restrict__ wd7,
    const float* __restrict__ wo3, const float* __restrict__ wm3,
    const float* __restrict__ wo5, const float* __restrict__ wm5,
    const float* __restrict__ wo7, const float* __restrict__ wm7) {
    int idx = blockIdx.x * 256 + threadIdx.x;
    if (idx < S_WT) {
        const float* w; float* dst; int kk;
        if (idx < 9 * 4096) { w = wd3; dst = g_wt3; kk = 9; }
        else if (idx < 34 * 4096) { idx -= 9 * 4096; w = wd5; dst = g_wt5; kk = 25; }
        else { idx -= 34 * 4096; w = wd7; dst = g_wt7; kk = 49; }
        int oc = idx & 63;
        int rem = idx >> 6;
        int c = rem & 63;
        int t = rem >> 6;
        dst[idx] = f2tff(w[(oc * 64 + c) * kk + t]);
        return;
    }
    idx -= S_WT;
    if (idx < S_WA) {
        const float* wo; const float* wm; float* dst; int kk, ocw;
        if (idx < 576 * 32) { wo = wo3; wm = wm3; dst = g_wa3; kk = 9; ocw = 32; }
        else if (idx < 576 * 32 + 1600 * 96) {
            idx -= 576 * 32; wo = wo5; wm = wm5; dst = g_wa5; kk = 25; ocw = 96;
        } else {
            idx -= 576 * 32 + 1600 * 96; wo = wo7; wm = wm7; dst = g_wa7; kk = 49; ocw = 160;
        }
        int oc = idx % ocw;
        int k = idx / ocw;
        int t = k >> 6;
        int c = k & 63;
        float v = 0.f;
        if (oc < 2 * kk) v = wo[(oc * 64 + c) * kk + t];
        else if (oc < 3 * kk) v = wm[((oc - 2 * kk) * 64 + c) * kk + t];
        dst[idx] = f2tff(v);
        return;
    }
    idx -= S_WA;
    if (idx < S_XP) {
        int pp = idx % PHW2;
        int bc = idx / PHW2;
        int yp = pp / PH - 3;
        int xp = pp % PH - 3;
        float v = 0.f;
        if (yp >= 0 && yp < HH && xp >= 0 && xp < WW)
            v = f2tff(__ldg(x + bc * HWSZ + yp * WW + xp));
        g_xpad[idx] = v;
    }
}

// ---------------- conv phase: 32 oc x 128 pix per CTA, [t][c] K-order --------
template <int K, int OCW>
__device__ __forceinline__ void conv_branch(
    const float* __restrict__ b_off, const float* __restrict__ b_mask,
    float* As, float* Bs, int ocbase, int b, int pbase) {
    constexpr int KK = K * K;
    constexpr int P = K / 2;
    constexpr int NCH = 2 * KK;     // 32-deep chunks
    constexpr int AST = 36;
    constexpr int BST = 36;

    const int tid = threadIdx.x;
    const int wid = tid >> 5;
    const int lane = tid & 31;
    const int g = lane >> 2;
    const int tg = lane & 3;
    const int mbase = (wid & 1) * 16;
    const int nbase = (wid >> 1) * 32;

    // staging ids
    const int ak = tid >> 3;           // A: k row 0..31
    const int ao4 = (tid & 7) * 4;     // A: 4 oc
    const int bpix = tid & 127;        // B: pixel
    const int bkh = (tid >> 7) * 16;   // B: k half 0/16
    const int phw = pbase + bpix;
    const int ph = phw / WW;
    const int pw = phw - ph * WW;
    const int pbase86 = (ph + 3 - P) * PH + (pw + 3 - P);
    const float* xpb = g_xpad + b * CI * PHW2;
    const float* wa = wa_buf<K>();

    auto stage = [&](int n, int buf) {
        float* Ab = As + buf * 32 * AST;
        float* Bb = Bs + buf * 128 * BST;
        // A: coalesced float4 copy
        *(float4*)(Ab + ak * AST + ao4) =
            *(const float4*)(wa + (n * 32 + ak) * OCW + ocbase + ao4);
        // B: one tap per chunk -> branch-free strided loads
        const int t = n >> 1;
        const int c0 = (n & 1) * 32 + bkh;
        const int ky = t / K;
        const int kx = t - ky * K;
        const float* src = xpb + pbase86 + ky * PH + kx + c0 * PHW2;
        float v[16];
#pragma unroll
        for (int j = 0; j < 16; ++j) v[j] = __ldg(src + j * PHW2);
        float* dst = Bb + bpix * BST + bkh;
#pragma unroll
        for (int q = 0; q < 4; ++q)
            *(float4*)(dst + q * 4) =
                make_float4(v[q * 4], v[q * 4 + 1], v[q * 4 + 2], v[q * 4 + 3]);
    };

    float acc[4][4];
#pragma unroll
    for (int i = 0; i < 4; ++i)
#pragma unroll
        for (int l = 0; l < 4; ++l) acc[i][l] = 0.f;

    stage(0, 0);
    __syncthreads();
    for (int n = 0; n < NCH; ++n) {
        if (n + 1 < NCH) stage(n + 1, (n + 1) & 1);
        mma_chunk32<AST, BST>(As + (n & 1) * 32 * AST, Bs + (n & 1) * 128 * BST,
                              mbase, nbase, g, tg, acc);
        __syncthreads();
    }

    // epilogue
#pragma unroll
    for (int r = 0; r < 2; ++r) {
        int ocl = ocbase + mbase + g + r * 8;
        float* dst;
        float bias;
        bool msk;
        if (ocl < 2 * KK) {
            dst = off_buf<K>() + ((size_t)(b * 2 * KK + ocl)) * HWSZ;
            bias = __ldg(b_off + ocl);
            msk = false;
        } else if (ocl < 3 * KK) {
            dst = mask_buf<K>() + ((size_t)(b * KK + (ocl - 2 * KK))) * HWSZ;
            bias = __ldg(b_mask + (ocl - 2 * KK));
            msk = true;
        } else continue;
#pragma unroll
        for (int nt = 0; nt < 4; ++nt) {
            int col = pbase + nbase + nt * 8 + tg * 2;
            float f0 = acc[nt][r * 2] + bias;
            float f1 = acc[nt][r * 2 + 1] + bias;
            if (msk) {
                f0 = 1.f / (1.f + __expf(-f0));
                f1 = 1.f / (1.f + __expf(-f1));
            }
            *(float2*)(dst + col) = make_float2(f0, f1);
        }
    }
}

__global__ __launch_bounds__(256) void conv_tc(
    const float* __restrict__ b_off3, const float* __restrict__ b_mask3,
    const float* __restrict__ b_off5, const float* __restrict__ b_mask5,
    const float* __restrict__ b_off7, const float* __restrict__ b_mask7) {
    __shared__ float As[2 * 32 * 36];
    __shared__ float Bs[2 * 128 * 36];
    const int yb = blockIdx.y;
    const int b = blockIdx.z;
    const int pbase = blockIdx.x * 128;
    if (yb == 0)
        conv_branch<3, 32>(b_off3, b_mask3, As, Bs, 0, b, pbase);
    else if (yb < 4)
        conv_branch<5, 96>(b_off5, b_mask5, As, Bs, (yb - 1) * 32, b, pbase);
    else
        conv_branch<7, 160>(b_off7, b_mask7, As, Bs, (yb - 4) * 32, b, pbase);
}

// ---------------- deform phase: 64 oc x 64 pix per CTA, mma tf32 -------------
template <int K, int BROFF>
__device__ __forceinline__ void deform_branch(
    const float* __restrict__ x, float* __restrict__ out,
    float* As, float* Bs, int b, int pbase) {
    constexpr int KK = K * K;
    constexpr int P = K / 2;
    constexpr int NCH = KK * 2;     // 32-deep chunks, 2 per tap
    constexpr int AST = 68;
    constexpr int BST = 36;

    const int tid = threadIdx.x;
    const int wid = tid >> 5;
    const int lane = tid & 31;
    const int g = lane >> 2;
    const int tg = lane & 3;
    const int mbase = (wid & 3) * 16;
    const int nbase = (wid >> 2) * 32;

    const int sp = tid & 63;           // staging pixel (B) / oc (A col)
    const int cg = tid >> 6;           // 0..3
    const int shw = pbase + sp;
    const int sh = shw / WW;
    const int swp = shw - sh * WW;
    const float* xb = x + b * CI * HWSZ;
    const float* wt = wt_buf<K>();
    const float* goff = off_buf<K>();
    const float* gmask = mask_buf<K>();

    float r_oy, r_ox, r_m;
    float4 dw;
    int4 di;

    auto prefetch_raw = [&](int t) {
        if (t < KK) {
            r_oy = __ldg(goff + (b * 2 * KK + 2 * t) * HWSZ + shw);
            r_ox = __ldg(goff + (b * 2 * KK + 2 * t + 1) * HWSZ + shw);
            r_m = __ldg(gmask + (b * KK + t) * HWSZ + shw);
        }
    };
    auto finalize_desc = [&](int t) {
        int ty = t / K, tx = t - ty * K;
        float py = (float)(sh - P + ty) + r_oy;
        float px = (float)(swp - P + tx) + r_ox;
        float y0f = floorf(py), x0f = floorf(px);
        float wy1 = py - y0f, wx1 = px - x0f;
        float wy0 = 1.f - wy1, wx0 = 1.f - wx1;
        float vy0 = (y0f >= 0.f && y0f <= (float)(HH - 1)) ? 1.f : 0.f;
        float vy1 = (y0f >= -1.f && y0f <= (float)(HH - 2)) ? 1.f : 0.f;
        float vx0 = (x0f >= 0.f && x0f <= (float)(WW - 1)) ? 1.f : 0.f;
        float vx1 = (x0f >= -1.f && x0f <= (float)(WW - 2)) ? 1.f : 0.f;
        int y0 = min(max((int)y0f, 0), HH - 1);
        int y1 = min(max((int)y0f + 1, 0), HH - 1);
        int x0 = min(max((int)x0f, 0), WW - 1);
        int x1 = min(max((int)x0f + 1, 0), WW - 1);
        dw = make_float4(wy0 * wx0 * vy0 * vx0 * r_m,
                         wy0 * wx1 * vy0 * vx1 * r_m,
                         wy1 * wx0 * vy1 * vx0 * r_m,
                         wy1 * wx1 * vy1 * vx1 * r_m);
        di = make_int4(y0 * WW + x0, y0 * WW + x1, y1 * WW + x0, y1 * WW + x1);
    };

    auto stage = [&](int n, int buf) {
        const int t = n >> 1;
        const int cb = (n & 1) * 32;
        if ((n & 1) == 0) {
            finalize_desc(t);
            prefetch_raw(t + 1);
        }
        float* Ab = As + buf * 32 * AST;
        float* Bb = Bs + buf * 64 * BST;
        // A: weights [32 c][64 oc], coalesced (oc=sp, rows cg*8..cg*8+7)
#pragma unroll
        for (int i = 0; i < 8; ++i) {
            int cr = cg * 8 + i;
            Ab[cr * AST + sp] = __ldg(wt + (t * 64 + cb + cr) * 64 + sp);
        }
        // B: bilinear-gathered activations, 8 channels per thread
        float bv[8];
#pragma unroll
        for (int i = 0; i < 8; ++i) {
            const float* base = xb + (cb + cg * 8 + i) * HWSZ;
            float v = dw.x * __ldg(base + di.x) + dw.y * __ldg(base + di.y) +
                      dw.z * __ldg(base + di.z) + dw.w * __ldg(base + di.w);
            bv[i] = f2tff(v);
        }
        float* dst = Bb + sp * BST + cg * 8;
        *(float4*)(dst) = make_float4(bv[0], bv[1], bv[2], bv[3]);
        *(float4*)(dst + 4) = make_float4(bv[4], bv[5], bv[6], bv[7]);
    };

    float acc[4][4];
#pragma unroll
    for (int i = 0; i < 4; ++i)
#pragma unroll
        for (int l = 0; l < 4; ++l) acc[i][l] = 0.f;

    prefetch_raw(0);
    stage(0, 0);
    __syncthreads();
    for (int n = 0; n < NCH; ++n) {
        if (n + 1 < NCH) stage(n + 1, (n + 1) & 1);
        mma_chunk32<AST, BST>(As + (n & 1) * 32 * AST, Bs + (n & 1) * 64 * BST,
                              mbase, nbase, g, tg, acc);
        __syncthreads();
    }

#pragma unroll
    for (int r = 0; r < 2; ++r) {
        int ocl = BROFF + mbase + g + r * 8;
        float* dst = out + ((size_t)(b * 192 + ocl)) * HWSZ;
#pragma unroll
        for (int nt = 0; nt < 4; ++nt) {
            int col = pbase + nbase + nt * 8 + tg * 2;
            *(float2*)(dst + col) = make_float2(acc[nt][r * 2], acc[nt][r * 2 + 1]);
        }
    }
}

__global__ __launch_bounds__(256) void deform_tc(
    const float* __restrict__ x, float* __restrict__ out) {
    __shared__ float As[2 * 32 * 68];
    __shared__ float Bs[2 * 64 * 36];
    const int br = blockIdx.y;
    const int b = blockIdx.z;
    const int pbase = blockIdx.x * 64;
    if (br == 0) deform_branch<3, 0>(x, out, As, Bs, b, pbase);
    else if (br == 1) deform_branch<5, 64>(x, out, As, Bs, b, pbase);
    else deform_branch<7, 128>(x, out, As, Bs, b, pbase);
}

extern "C" void kernel_launch(void* const* d_in, const int* in_sizes, int n_in,
                              void* d_out, int out_size) {
    (void)in_sizes; (void)n_in; (void)out_size;
    const float* x       = (const float*)d_in[0];
    const float* w_off3  = (const float*)d_in[1];
    const float* b_off3  = (const float*)d_in[2];
    const float* w_mask3 = (const float*)d_in[3];
    const float* b_mask3 = (const float*)d_in[4];
    const float* w_dcn3  = (const float*)d_in[5];
    const float* w_off5  = (const float*)d_in[6];
    const float* b_off5  = (const float*)d_in[7];
    const float* w_mask5 = (const float*)d_in[8];
    const float* b_mask5 = (const float*)d_in[9];
    const float* w_dcn5  = (const float*)d_in[10];
    const float* w_off7  = (const float*)d_in[11];
    const float* b_off7  = (const float*)d_in[12];
    const float* w_mask7 = (const float*)d_in[13];
    const float* b_mask7 = (const float*)d_in[14];
    const float* w_dcn7  = (const float*)d_in[15];
    float* out = (float*)d_out;

    const int prep_total = S_WT + S_WA + S_XP;
    prep_all<<<(prep_total + 255) / 256, 256>>>(
        x, w_dcn3, w_dcn5, w_dcn7,
        w_off3, w_mask3, w_off5, w_mask5, w_off7, w_mask7);

    conv_tc<<<dim3(50, 9, NB), 256>>>(
        b_off3, b_mask3, b_off5, b_mask5, b_off7, b_mask7);

    deform_tc<<<dim3(100, 3, NB), 256>>>(x, out);
}

// round 6
// speedup vs baseline: 2.9265x; 1.2205x over previous
#include <cuda_runtime.h>
#include <cstdint>

#define HH 80
#define WW 80
#define HWSZ 6400
#define NB 2
#define CI 64
#define PH 86
#define PHW2 7396   // 86*86

// ---------------- scratch (__device__ globals; no allocation) ----------------
__device__ float g_off3[NB * 18 * HWSZ];
__device__ float g_mask3[NB * 9 * HWSZ];
__device__ float g_off5[NB * 50 * HWSZ];
__device__ float g_mask5[NB * 25 * HWSZ];
__device__ float g_off7[NB * 98 * HWSZ];
__device__ float g_mask7[NB * 49 * HWSZ];
__device__ float g_wt3[9 * 64 * 64];    // [t][c][oc], tf32-rounded (deform A)
__device__ float g_wt5[25 * 64 * 64];
__device__ float g_wt7[49 * 64 * 64];
__device__ float g_wa3[576 * 32];       // conv A: [k=(t,c)][ocpad], tf32
__device__ float g_wa5[1600 * 96];
__device__ float g_wa7[3136 * 160];
__device__ float g_xpad[NB * CI * PHW2];  // padded + tf32-rounded image

template <int K> __device__ __forceinline__ float* off_buf() {
    if constexpr (K == 3) return g_off3;
    else if constexpr (K == 5) return g_off5;
    else return g_off7;
}
template <int K> __device__ __forceinline__ float* mask_buf() {
    if constexpr (K == 3) return g_mask3;
    else if constexpr (K == 5) return g_mask5;
    else return g_mask7;
}
template <int K> __device__ __forceinline__ float* wt_buf() {
    if constexpr (K == 3) return g_wt3;
    else if constexpr (K == 5) return g_wt5;
    else return g_wt7;
}
template <int K> __device__ __forceinline__ float* wa_buf() {
    if constexpr (K == 3) return g_wa3;
    else if constexpr (K == 5) return g_wa5;
    else return g_wa7;
}

// ---------------- tf32 helpers ----------------
__device__ __forceinline__ uint32_t f2tf(float x) {
    uint32_t u;
    asm("cvt.rna.tf32.f32 %0, %1;" : "=r"(u) : "f"(x));
    return u;
}
__device__ __forceinline__ float f2tff(float x) { return __uint_as_float(f2tf(x)); }

__device__ __forceinline__ void mma8(float c[4], uint32_t a0, uint32_t a1,
                                     uint32_t a2, uint32_t a3,
                                     uint32_t b0, uint32_t b1) {
    asm volatile(
        "mma.sync.aligned.m16n8k8.row.col.f32.tf32.tf32.f32 "
        "{%0,%1,%2,%3},{%4,%5,%6,%7},{%8,%9},{%0,%1,%2,%3};"
        : "+f"(c[0]), "+f"(c[1]), "+f"(c[2]), "+f"(c[3])
        : "r"(a0), "r"(a1), "r"(a2), "r"(a3), "r"(b0), "r"(b1));
}

// ---------------- single prep kernel: wt transpose, conv-A prep, xpad --------
#define S_WT 339968          // (9+25+49)*4096
#define S_WA 673792          // 576*32 + 1600*96 + 3136*160
#define S_XP (NB * CI * PHW2)
__global__ __launch_bounds__(256) void prep_all(
    const float* __restrict__ x,
    const float* __restrict__ wd3, const float* __restrict__ wd5,
    const float* __restrict__ wd7,
    const float* __restrict__ wo3, const float* __restrict__ wm3,
    const float* __restrict__ wo5, const float* __restrict__ wm5,
    const float* __restrict__ wo7, const float* __restrict__ wm7) {
    int idx = blockIdx.x * 256 + threadIdx.x;
    if (idx < S_WT) {
        const float* w; float* dst; int kk;
        if (idx < 9 * 4096) { w = wd3; dst = g_wt3; kk = 9; }
        else if (idx < 34 * 4096) { idx -= 9 * 4096; w = wd5; dst = g_wt5; kk = 25; }
        else { idx -= 34 * 4096; w = wd7; dst = g_wt7; kk = 49; }
        int oc = idx & 63;
        int rem = idx >> 6;
        int c = rem & 63;
        int t = rem >> 6;
        dst[idx] = f2tff(w[(oc * 64 + c) * kk + t]);
        return;
    }
    idx -= S_WT;
    if (idx < S_WA) {
        const float* wo; const float* wm; float* dst; int kk, ocw;
        if (idx < 576 * 32) { wo = wo3; wm = wm3; dst = g_wa3; kk = 9; ocw = 32; }
        else if (idx < 576 * 32 + 1600 * 96) {
            idx -= 576 * 32; wo = wo5; wm = wm5; dst = g_wa5; kk = 25; ocw = 96;
        } else {
            idx -= 576 * 32 + 1600 * 96; wo = wo7; wm = wm7; dst = g_wa7; kk = 49; ocw = 160;
        }
        int oc = idx % ocw;
        int k = idx / ocw;
        int t = k >> 6;
        int c = k & 63;
        float v = 0.f;
        if (oc < 2 * kk) v = wo[(oc * 64 + c) * kk + t];
        else if (oc < 3 * kk) v = wm[((oc - 2 * kk) * 64 + c) * kk + t];
        dst[idx] = f2tff(v);
        return;
    }
    idx -= S_WA;
    if (idx < S_XP) {
        int pp = idx % PHW2;
        int bc = idx / PHW2;
        int yp = pp / PH - 3;
        int xp = pp % PH - 3;
        float v = 0.f;
        if (yp >= 0 && yp < HH && xp >= 0 && xp < WW)
            v = f2tff(__ldg(x + bc * HWSZ + yp * WW + xp));
        g_xpad[idx] = v;
    }
}

// ---------------- conv phase: G oc-groups x 128 pix per CTA ------------------
// B smem: [n=128][k32 pair-interleaved] stride 36; within each 8-group of k,
// position = (k&3)*2 + ((k>>2)&1), so b-frag (k, k+4) is one aligned float2.
template <int K, int G, int OCW, int OCB>
__device__ __forceinline__ void conv_branch(
    const float* __restrict__ b_off, const float* __restrict__ b_mask,
    float* smem, int b, int pbase) {
    constexpr int KK = K * K;
    constexpr int P = K / 2;
    constexpr int NCH = 2 * KK;
    constexpr int MST = G * 32 + 4;

    float* As = smem;                    // 2 * 32 * MST
    float* Bs = smem + 2 * 32 * MST;     // 2 * 128 * 36

    const int tid = threadIdx.x;
    const int wid = tid >> 5;
    const int lane = tid & 31;
    const int g = lane >> 2;
    const int tg = lane & 3;
    const int mbase = (wid & 1) * 16;
    const int nbase = (wid >> 1) * 32;

    // staging ids
    const int ak = tid >> 3;           // A: k row 0..31
    const int ao4 = (tid & 7) * 4;     // A: 4 oc within group
    const int bpix = tid & 127;        // B: pixel
    const int bkh = (tid >> 7) * 16;   // B: k half 0/16
    const int phw = pbase + bpix;
    const int ph = phw / WW;
    const int pw = phw - ph * WW;
    const int pbase86 = (ph + 3 - P) * PH + (pw + 3 - P);
    const float* xpb = g_xpad + b * CI * PHW2;
    const float* wa = wa_buf<K>();

    auto stage = [&](int n, int buf) {
        float* Ab = As + buf * 32 * MST;
        float* Bb = Bs + buf * 128 * 36;
#pragma unroll
        for (int gi = 0; gi < G; ++gi)
            *(float4*)(Ab + ak * MST + gi * 32 + ao4) =
                *(const float4*)(wa + (n * 32 + ak) * OCW + OCB + gi * 32 + ao4);
        const int t = n >> 1;
        const int c0 = (n & 1) * 32 + bkh;
        const int ky = t / K;
        const int kx = t - ky * K;
        const float* src = xpb + pbase86 + ky * PH + kx + c0 * PHW2;
        float v[16];
#pragma unroll
        for (int j = 0; j < 16; ++j) v[j] = __ldg(src + j * PHW2);
        float* dst = Bb + bpix * 36 + bkh;
#pragma unroll
        for (int q = 0; q < 2; ++q)
#pragma unroll
            for (int s = 0; s < 4; ++s)
                *(float2*)(dst + q * 8 + s * 2) =
                    make_float2(v[q * 8 + s], v[q * 8 + s + 4]);
    };

    float acc[G][4][4];
#pragma unroll
    for (int gi = 0; gi < G; ++gi)
#pragma unroll
        for (int i = 0; i < 4; ++i)
#pragma unroll
            for (int l = 0; l < 4; ++l) acc[gi][i][l] = 0.f;

    stage(0, 0);
    __syncthreads();
    for (int n = 0; n < NCH; ++n) {
        if (n + 1 < NCH) stage(n + 1, (n + 1) & 1);
        const float* Ab = As + (n & 1) * 32 * MST;
        const float* Bb = Bs + (n & 1) * 128 * 36;
#pragma unroll
        for (int ks = 0; ks < 32; ks += 8) {
            float2 bb[4];
#pragma unroll
            for (int nt = 0; nt < 4; ++nt)
                bb[nt] = *(const float2*)(Bb + (nbase + nt * 8 + g) * 36 + ks + tg * 2);
#pragma unroll
            for (int gi = 0; gi < G; ++gi) {
                const int mb = gi * 32 + mbase + g;
                uint32_t a0 = __float_as_uint(Ab[(ks + tg) * MST + mb]);
                uint32_t a1 = __float_as_uint(Ab[(ks + tg) * MST + mb + 8]);
                uint32_t a2 = __float_as_uint(Ab[(ks + tg + 4) * MST + mb]);
                uint32_t a3 = __float_as_uint(Ab[(ks + tg + 4) * MST + mb + 8]);
#pragma unroll
                for (int nt = 0; nt < 4; ++nt)
                    mma8(acc[gi][nt], a0, a1, a2, a3,
                         __float_as_uint(bb[nt].x), __float_as_uint(bb[nt].y));
            }
        }
        __syncthreads();
    }

    // epilogue
#pragma unroll
    for (int gi = 0; gi < G; ++gi)
#pragma unroll
        for (int r = 0; r < 2; ++r) {
            int ocl = OCB + gi * 32 + mbase + g + r * 8;
            float* dst;
            float bias;
            bool msk;
            if (ocl < 2 * KK) {
                dst = off_buf<K>() + ((size_t)(b * 2 * KK + ocl)) * HWSZ;
                bias = __ldg(b_off + ocl);
                msk = false;
            } else if (ocl < 3 * KK) {
                dst = mask_buf<K>() + ((size_t)(b * KK + (ocl - 2 * KK))) * HWSZ;
                bias = __ldg(b_mask + (ocl - 2 * KK));
                msk = true;
            } else continue;
#pragma unroll
            for (int nt = 0; nt < 4; ++nt) {
                int col = pbase + nbase + nt * 8 + tg * 2;
                float f0 = acc[gi][nt][r * 2] + bias;
                float f1 = acc[gi][nt][r * 2 + 1] + bias;
                if (msk) {
                    f0 = 1.f / (1.f + __expf(-f0));
                    f1 = 1.f / (1.f + __expf(-f1));
                }
                *(float2*)(dst + col) = make_float2(f0, f1);
            }
        }
}

// cid map pairs heavy CTAs with light ones (i co-resides with i+148):
// 0-99: k7 G=3 | 148-247: k7 G=2 | 100-147 & 248-299: k5 | 300-399: k3
__global__ __launch_bounds__(256, 2) void conv_tc(
    const float* __restrict__ b_off3, const float* __restrict__ b_mask3,
    const float* __restrict__ b_off5, const float* __restrict__ b_mask5,
    const float* __restrict__ b_off7, const float* __restrict__ b_mask7) {
    extern __shared__ float dynsmem[];
    const int cid = blockIdx.x;
    int j, kind;
    if (cid < 100) { j = cid; kind = 0; }
    else if (cid < 148) { j = cid - 100; kind = 2; }
    else if (cid < 248) { j = cid - 148; kind = 1; }
    else if (cid < 300) { j = cid - 200; kind = 2; }
    else { j = cid - 300; kind = 3; }
    const int b = j / 50;
    const int pbase = (j % 50) * 128;
    if (kind == 0)
        conv_branch<7, 3, 160, 0>(b_off7, b_mask7, dynsmem, b, pbase);
    else if (kind == 1)
        conv_branch<7, 2, 160, 96>(b_off7, b_mask7, dynsmem, b, pbase);
    else if (kind == 2)
        conv_branch<5, 3, 96, 0>(b_off5, b_mask5, dynsmem, b, pbase);
    else
        conv_branch<3, 1, 32, 0>(b_off3, b_mask3, dynsmem, b, pbase);
}

// ---------------- deform phase: 64 oc x 128 pix per CTA ----------------------
template <int K, int BROFF>
__device__ __forceinline__ void deform_branch(
    const float* __restrict__ x, float* __restrict__ out,
    float* smem, int b, int pbase) {
    constexpr int KK = K * K;
    constexpr int P = K / 2;
    constexpr int NCH = KK * 2;
    constexpr int AST = 68;

    float* As = smem;                   // 2 * 32 * 68
    float* Bs = smem + 2 * 32 * AST;    // 2 * 128 * 36

    const int tid = threadIdx.x;
    const int wid = tid >> 5;
    const int lane = tid & 31;
    const int g = lane >> 2;
    const int tg = lane & 3;
    const int mbase = (wid & 1) * 32;   // 2 m-groups of 32
    const int nbase = (wid >> 1) * 32;  // 4 n-groups of 32

    // staging ids
    const int pix = tid & 127;
    const int kh = (tid >> 7) * 16;
    const int arow = tid >> 3;          // A: c row 0..31
    const int ac8 = (tid & 7) * 8;      // A: 8 oc
    const int shw = pbase + pix;
    const int sh = shw / WW;
    const int swp = shw - sh * WW;
    const float* xb = x + b * CI * HWSZ;
    const float* wt = wt_buf<K>();
    const float* goff = off_buf<K>();
    const float* gmask = mask_buf<K>();

    float r_oy, r_ox, r_m;
    float4 dw;
    int4 di;

    auto prefetch_raw = [&](int t) {
        if (t < KK) {
            r_oy = __ldg(goff + (b * 2 * KK + 2 * t) * HWSZ + shw);
            r_ox = __ldg(goff + (b * 2 * KK + 2 * t + 1) * HWSZ + shw);
            r_m = __ldg(gmask + (b * KK + t) * HWSZ + shw);
        }
    };
    auto finalize_desc = [&](int t) {
        int ty = t / K, tx = t - ty * K;
        float py = (float)(sh - P + ty) + r_oy;
        float px = (float)(swp - P + tx) + r_ox;
        float y0f = floorf(py), x0f = floorf(px);
        float wy1 = py - y0f, wx1 = px - x0f;
        float wy0 = 1.f - wy1, wx0 = 1.f - wx1;
        float vy0 = (y0f >= 0.f && y0f <= (float)(HH - 1)) ? 1.f : 0.f;
        float vy1 = (y0f >= -1.f && y0f <= (float)(HH - 2)) ? 1.f : 0.f;
        float vx0 = (x0f >= 0.f && x0f <= (float)(WW - 1)) ? 1.f : 0.f;
        float vx1 = (x0f >= -1.f && x0f <= (float)(WW - 2)) ? 1.f : 0.f;
        int y0 = min(max((int)y0f, 0), HH - 1);
        int y1 = min(max((int)y0f + 1, 0), HH - 1);
        int x0 = min(max((int)x0f, 0), WW - 1);
        int x1 = min(max((int)x0f + 1, 0), WW - 1);
        dw = make_float4(wy0 * wx0 * vy0 * vx0 * r_m,
                         wy0 * wx1 * vy0 * vx1 * r_m,
                         wy1 * wx0 * vy1 * vx0 * r_m,
                         wy1 * wx1 * vy1 * vx1 * r_m);
        di = make_int4(y0 * WW + x0, y0 * WW + x1, y1 * WW + x0, y1 * WW + x1);
    };

    auto stage = [&](int n, int buf) {
        const int t = n >> 1;
        const int cb = (n & 1) * 32;
        if ((n & 1) == 0) {
            finalize_desc(t);
            prefetch_raw(t + 1);
        }
        float* Ab = As + buf * 32 * AST;
        float* Bb = Bs + buf * 128 * 36;
        // A: [32 c][64 oc], two float4 per thread, coalesced
        const float* wrow = wt + (t * 64 + cb + arow) * 64 + ac8;
        *(float4*)(Ab + arow * AST + ac8) = *(const float4*)(wrow);
        *(float4*)(Ab + arow * AST + ac8 + 4) = *(const float4*)(wrow + 4);
        // B: bilinear gather, 16 channels of this thread's pixel
        float v[16];
#pragma unroll
        for (int i = 0; i < 16; ++i) {
            const float* base = xb + (cb + kh + i) * HWSZ;
            float s = dw.x * __ldg(base + di.x) + dw.y * __ldg(base + di.y) +
                      dw.z * __ldg(base + di.z) + dw.w * __ldg(base + di.w);
            v[i] = f2tff(s);
        }
        float* dst = Bb + pix * 36 + kh;
#pragma unroll
        for (int q = 0; q < 2; ++q)
#pragma unroll
            for (int s = 0; s < 4; ++s)
                *(float2*)(dst + q * 8 + s * 2) =
                    make_float2(v[q * 8 + s], v[q * 8 + s + 4]);
    };

    float acc[2][4][4];
#pragma unroll
    for (int mt = 0; mt < 2; ++mt)
#pragma unroll
        for (int i = 0; i < 4; ++i)
#pragma unroll
            for (int l = 0; l < 4; ++l) acc[mt][i][l] = 0.f;

    prefetch_raw(0);
    stage(0, 0);
    __syncthreads();
    for (int n = 0; n < NCH; ++n) {
        if (n + 1 < NCH) stage(n + 1, (n + 1) & 1);
        const float* Ab = As + (n & 1) * 32 * AST;
        const float* Bb = Bs + (n & 1) * 128 * 36;
#pragma unroll
        for (int ks = 0; ks < 32; ks += 8) {
            float2 bb[4];
#pragma unroll
            for (int nt = 0; nt < 4; ++nt)
                bb[nt] = *(const float2*)(Bb + (nbase + nt * 8 + g) * 36 + ks + tg * 2);
#pragma unroll
            for (int mt = 0; mt < 2; ++mt) {
                const int mb = mbase + mt * 16 + g;
                uint32_t a0 = __float_as_uint(Ab[(ks + tg) * AST + mb]);
                uint32_t a1 = __float_as_uint(Ab[(ks + tg) * AST + mb + 8]);
                uint32_t a2 = __float_as_uint(Ab[(ks + tg + 4) * AST + mb]);
                uint32_t a3 = __float_as_uint(Ab[(ks + tg + 4) * AST + mb + 8]);
#pragma unroll
                for (int nt = 0; nt < 4; ++nt)
                    mma8(acc[mt][nt], a0, a1, a2, a3,
                         __float_as_uint(bb[nt].x), __float_as_uint(bb[nt].y));
            }
        }
        __syncthreads();
    }

#pragma unroll
    for (int mt = 0; mt < 2; ++mt)
#pragma unroll
        for (int r = 0; r < 2; ++r) {
            int ocl = BROFF + mbase + mt * 16 + g + r * 8;
            float* dst = out + ((size_t)(b * 192 + ocl)) * HWSZ;
#pragma unroll
            for (int nt = 0; nt < 4; ++nt) {
                int col = pbase + nbase + nt * 8 + tg * 2;
                *(float2*)(dst + col) =
                    make_float2(acc[mt][nt][r * 2], acc[mt][nt][r * 2 + 1]);
            }
        }
}

// cid map: 0-99 k7 | 148-247 k3 | 100-147 & 248-299 k5 (k7 pairs with k3)
__global__ __launch_bounds__(256, 2) void deform_tc(
    const float* __restrict__ x, float* __restrict__ out) {
    extern __shared__ float dynsmem[];
    const int cid = blockIdx.x;
    int j, kind;
    if (cid < 100) { j = cid; kind = 0; }
    else if (cid < 148) { j = cid - 100; kind = 2; }
    else if (cid < 248) { j = cid - 148; kind = 1; }
    else { j = cid - 200; kind = 2; }
    const int b = j / 50;
    const int pbase = (j % 50) * 128;
    if (kind == 0) deform_branch<7, 128>(x, out, dynsmem, b, pbase);
    else if (kind == 1) deform_branch<3, 0>(x, out, dynsmem, b, pbase);
    else deform_branch<5, 64>(x, out, dynsmem, b, pbase);
}

extern "C" void kernel_launch(void* const* d_in, const int* in_sizes, int n_in,
                              void* d_out, int out_size) {
    (void)in_sizes; (void)n_in; (void)out_size;
    const float* x       = (const float*)d_in[0];
    const float* w_off3  = (const float*)d_in[1];
    const float* b_off3  = (const float*)d_in[2];
    const float* w_mask3 = (const float*)d_in[3];
    const float* b_mask3 = (const float*)d_in[4];
    const float* w_dcn3  = (const float*)d_in[5];
    const float* w_off5  = (const float*)d_in[6];
    const float* b_off5  = (const float*)d_in[7];
    const float* w_mask5 = (const float*)d_in[8];
    const float* b_mask5 = (const float*)d_in[9];
    const float* w_dcn5  = (const float*)d_in[10];
    const float* w_off7  = (const float*)d_in[11];
    const float* b_off7  = (const float*)d_in[12];
    const float* w_mask7 = (const float*)d_in[13];
    const float* b_mask7 = (const float*)d_in[14];
    const float* w_dcn7  = (const float*)d_in[15];
    float* out = (float*)d_out;

    // conv: max G=3 -> 2*32*100*4 + 2*128*36*4 = 62464 bytes
    // deform: 2*32*68*4 + 2*128*36*4 = 54272 bytes
    const int conv_smem = 2 * 32 * 100 * 4 + 2 * 128 * 36 * 4;
    const int def_smem = 2 * 32 * 68 * 4 + 2 * 128 * 36 * 4;
    cudaFuncSetAttribute(conv_tc, cudaFuncAttributeMaxDynamicSharedMemorySize,
                         conv_smem);
    cudaFuncSetAttribute(deform_tc, cudaFuncAttributeMaxDynamicSharedMemorySize,
                         def_smem);

    const int prep_total = S_WT + S_WA + S_XP;
    prep_all<<<(prep_total + 255) / 256, 256>>>(
        x, w_dcn3, w_dcn5, w_dcn7,
        w_off3, w_mask3, w_off5, w_mask5, w_off7, w_mask7);

    conv_tc<<<400, 256, conv_smem>>>(
        b_off3, b_mask3, b_off5, b_mask5, b_off7, b_mask7);

    deform_tc<<<300, 256, def_smem>>>(x, out);
}